// round 14
// baseline (speedup 1.0000x reference)
#include <cuda_runtime.h>
#include <cstdint>

// qkv scratch in windowed layout: [b(2)][wy(16)][wx(16)][ch(56)][Bs(8)][tok(64)]
#define NELEM_QKV (2*16*16*56*8*64)
__device__ float g_q[NELEM_QKV];
__device__ float g_k[NELEM_QKV];
__device__ float g_v[NELEM_QKV];
// sigma scratch: [win*4+head][Bs][64] (Sk stored PERMUTED), theta: [sbid*8+Bs]
__device__ float g_sq[2048 * 512];
__device__ float g_sk[2048 * 512];
__device__ float g_theta[16384];

__device__ __forceinline__ void cpa16(uint32_t dst, const void* src) {
  asm volatile("cp.async.ca.shared.global [%0], [%1], 16;"
               :: "r"(dst), "l"(src) : "memory");
}
__device__ __forceinline__ void cpa_commit() {
  asm volatile("cp.async.commit_group;" ::: "memory");
}
template <int N> __device__ __forceinline__ void cpa_wait() {
  asm volatile("cp.async.wait_group %0;" :: "n"(N) : "memory");
}

// ---------------------------------------------------------------------------
// All three grouped 3x3x3 convs, one launch (measured at its issue floor).
// ---------------------------------------------------------------------------
__global__ __launch_bounds__(256) void conv_all_kernel(
    const float* __restrict__ x, const float* __restrict__ last,
    const float* __restrict__ Wq, const float* __restrict__ Wk,
    const float* __restrict__ Wv)
{
  const int z = blockIdx.z;
  int idx, sel;
  if (z < 112) { idx = z; sel = 0; }
  else { int zz = z - 112; idx = zz >> 1; sel = 1 + (zz & 1); }
  const float* in = (sel == 0) ? x : last;
  const float* W3 = (sel == 0) ? Wq : (sel == 1) ? Wk : Wv;
  float* outw     = (sel == 0) ? g_q : (sel == 1) ? g_k : g_v;

  const int b = idx / 56, o = idx % 56;
  const int h = blockIdx.y * 8 + threadIdx.y;
  const int tx = threadIdx.x;
  const int w0 = tx * 4;

  __shared__ float ws[54];
  const int tid = threadIdx.y * 32 + tx;
  if (tid < 54) ws[tid] = W3[o * 54 + tid];
  __syncthreads();

  float acc[8][4];
#pragma unroll
  for (int i = 0; i < 8; i++) {
    acc[i][0] = 0.f; acc[i][1] = 0.f; acc[i][2] = 0.f; acc[i][3] = 0.f;
  }

#pragma unroll
  for (int ci = 0; ci < 2; ci++) {
    const float* basec = in + (size_t)((b * 112 + o * 2 + ci) * 8) * 16384;
#pragma unroll
    for (int dh = 0; dh < 3; dh++) {
      const int hh = h + dh - 1;
      if (hh < 0 || hh > 127) continue;
      float w9[3][3];
#pragma unroll
      for (int kd = 0; kd < 3; kd++)
#pragma unroll
        for (int dw = 0; dw < 3; dw++)
          w9[kd][dw] = ws[ci * 27 + kd * 9 + dh * 3 + dw];
      const float* rowp = basec + hh * 128 + w0;
#pragma unroll
      for (int d = 0; d < 8; d++) {
        const float* p = rowp + d * 16384;
        float4 m4 = *(const float4*)p;
        float vl = __shfl_up_sync(0xffffffffu, m4.w, 1);
        float vr = __shfl_down_sync(0xffffffffu, m4.x, 1);
        float v[6];
        v[0] = (tx == 0)  ? 0.f : vl;
        v[1] = m4.x; v[2] = m4.y; v[3] = m4.z; v[4] = m4.w;
        v[5] = (tx == 31) ? 0.f : vr;
#pragma unroll
        for (int kd = 0; kd < 3; kd++) {
          const int Bs = d + 1 - kd;
          if (Bs < 0 || Bs > 7) continue;
#pragma unroll
          for (int dw = 0; dw < 3; dw++) {
            const float wv = w9[kd][dw];
            acc[Bs][0] += wv * v[dw + 0];
            acc[Bs][1] += wv * v[dw + 1];
            acc[Bs][2] += wv * v[dw + 2];
            acc[Bs][3] += wv * v[dw + 3];
          }
        }
      }
    }
  }

  const int wy = h >> 3, ty = h & 7, wx = w0 >> 3, tx0 = w0 & 7;
  float* op = outw + (size_t)((((b * 16 + wy) * 16 + wx) * 56 + o) * 8) * 64
                   + ty * 8 + tx0;
#pragma unroll
  for (int Bs = 0; Bs < 8; Bs++) {
    *(float4*)(op + Bs * 64) =
        make_float4(acc[Bs][0], acc[Bs][1], acc[Bs][2], acc[Bs][3]);
  }
}

// ---------------------------------------------------------------------------
// Sigma kernel: Sq, Sk (permuted), theta for all 8 slices.
// t1_i = q_i.Kbar - m1_i*(q_i.k_i).
// ---------------------------------------------------------------------------
__global__ __launch_bounds__(256) void sigma_kernel(
    const float* __restrict__ pcq_w, const float* __restrict__ pcq_b,
    const float* __restrict__ pck_w, const float* __restrict__ pck_b,
    const float* __restrict__ mlp1_w, const float* __restrict__ mlp2_w1,
    const float* __restrict__ mlp2_w2)
{
  __shared__ __align__(16) float m1[64], w2[64];
  __shared__ __align__(16) float kbar_s[128];    // [Bs][16]
  __shared__ __align__(16) float t1_all[512];    // [Bs][64]
  __shared__ __align__(16) float red2[512];
  __shared__ float pcqw[14], pckw[14];

  const int tid = threadIdx.x;
  const int bid = blockIdx.x;               // win*4 + head
  const int head = bid & 3, win = bid >> 2;
  const int b = win >> 8, wy = (win >> 4) & 15, wx = win & 15;

  if (tid < 64) { m1[tid] = mlp1_w[tid]; w2[tid] = mlp2_w2[tid]; }
  if (tid < 14) { pcqw[tid] = pcq_w[tid]; pckw[tid] = pck_w[tid]; }
  const float bq = pcq_b[0], bk = pck_b[0];

  const size_t wbase = (size_t)((b * 16 + wy) * 16 + wx) * (56 * 8 * 64);
  const float* gqf = g_q + wbase + head * 14 * 512;
  const float* gkf = g_k + wbase + head * 14 * 512;
  const float4* gk = (const float4*)gkf;
  const float4* m14 = (const float4*)m1;
  const float4* t14 = (const float4*)t1_all;
  const float4* w14 = (const float4*)mlp2_w1;
  __syncthreads();

  // P1: Kbar[Bs][d]
#pragma unroll
  for (int rep = 0; rep < 2; rep++) {
    const int item = rep * 64 + (tid >> 2);
    const int p4 = tid & 3;
    if (item < 112) {
      const int Bs = item / 14, d = item % 14;
      float pr = 0.f;
#pragma unroll
      for (int c = 0; c < 4; c++) {
        float4 kv = gk[d * 128 + Bs * 16 + p4 * 4 + c];
        float4 mm = m14[p4 * 4 + c];
        pr += kv.x*mm.x + kv.y*mm.y + kv.z*mm.z + kv.w*mm.w;
      }
      pr += __shfl_xor_sync(0xffffffffu, pr, 1);
      pr += __shfl_xor_sync(0xffffffffu, pr, 2);
      if (p4 == 0) kbar_s[Bs * 16 + d] = pr;
    }
  }
  __syncthreads();

  // P2: per (Bs,i): Sq, Sk (permuted), t1
#pragma unroll
  for (int rep = 0; rep < 2; rep++) {
    const int t = tid + rep * 256;
    const int Bs = t >> 6, i = t & 63;
    float sq = bq, sk = bk, qkb = 0.f, dg = 0.f;
#pragma unroll
    for (int d = 0; d < 14; d++) {
      float qv = gqf[d * 512 + Bs * 64 + i];
      float kv = gkf[d * 512 + Bs * 64 + i];
      sq  += qv * pcqw[d];
      sk  += kv * pckw[d];
      qkb += qv * kbar_s[Bs * 16 + d];
      dg  += qv * kv;
    }
    g_sq[(size_t)bid * 512 + Bs * 64 + i] = sq;
    g_sk[(size_t)bid * 512 + Bs * 64 +
         ((((i >> 2) & 3) * 4 + (i >> 4)) * 4 + (i & 3))] = sk;
    t1_all[Bs * 64 + i] = qkb - m1[i] * dg;
  }
  __syncthreads();

  // P3: t2 = leaky(t1 @ w1^T); red2 = t2 * w2
#pragma unroll
  for (int rep = 0; rep < 2; rep++) {
    const int t = tid + rep * 256;
    const int Bs = t >> 6, o = t & 63;
    float s = 0.f;
#pragma unroll
    for (int c = 0; c < 16; c++) {
      float4 wv = __ldg(&w14[o * 16 + c]);
      float4 tv = t14[Bs * 16 + c];
      s += wv.x*tv.x + wv.y*tv.y + wv.z*tv.z + wv.w*tv.w;
    }
    s = (s > 0.f) ? s : 0.1f * s;
    red2[Bs * 64 + o] = s * w2[o];
  }
  __syncthreads();

  // P4: theta[Bs]
  {
    const int w = tid >> 5, lane = tid & 31;
    float s = red2[w * 64 + lane] + red2[w * 64 + lane + 32];
#pragma unroll
    for (int off = 16; off > 0; off >>= 1)
      s += __shfl_xor_sync(0xffffffffu, s, off);
    if (lane == 0) g_theta[bid * 8 + w] = s;
  }
}

// ---------------------------------------------------------------------------
// Attention: one block per (win, head) = 2048 long blocks, loop over 8 slices
// with cp.async double-buffered prefetch of q/k/v/Sk/Sq.
// ---------------------------------------------------------------------------
__global__ __launch_bounds__(256, 4) void attn_loop_kernel(
    const float* __restrict__ Wout, float* __restrict__ out)
{
  __shared__ __align__(16) float q_s[2][896], k_s[2][896], v_s[2][896];
  __shared__ __align__(16) float sim[64 * 68];
  __shared__ __align__(16) float sks_s[2][64], sq_s[2][64];
  __shared__ float woutc[28], theta_all[8];

  const int tid = threadIdx.x;
  const int bid = blockIdx.x;               // win*4 + head
  const int head = bid & 3, win = bid >> 2;
  const int b = win >> 8, wy = (win >> 4) & 15, wx = win & 15;
  const int sidx512 = bid * 512;

  const size_t wbase = (size_t)((b * 16 + wy) * 16 + wx) * (56 * 8 * 64);
  const float4* gq = (const float4*)(g_q + wbase + head * 14 * 512);
  const float4* gk = (const float4*)(g_k + wbase + head * 14 * 512);
  const float4* gv = (const float4*)(g_v + wbase + head * 14 * 512);

  float4* sim4 = (float4*)sim;

  if (tid < 28) woutc[tid] = Wout[head * 28 + tid];
  if (tid < 8)  theta_all[tid] = g_theta[bid * 8 + tid];

  // smem u32 bases for cp.async
  const uint32_t qb0 = (uint32_t)__cvta_generic_to_shared(&q_s[0][0]);
  const uint32_t kb0 = (uint32_t)__cvta_generic_to_shared(&k_s[0][0]);
  const uint32_t vb0 = (uint32_t)__cvta_generic_to_shared(&v_s[0][0]);
  const uint32_t skb0 = (uint32_t)__cvta_generic_to_shared(&sks_s[0][0]);
  const uint32_t sqb0 = (uint32_t)__cvta_generic_to_shared(&sq_s[0][0]);

  const int irow = tid >> 2, p4 = tid & 3;      // FG quad ownership
  const int wi = (tid >> 5) & 3, wj = tid >> 7; // C warp tile
  const int lane = tid & 31;
  const int it2 = lane >> 3, jt2 = lane & 7;
  const int hh = wy * 8 + (irow >> 3), ww = wx * 8 + (irow & 7);

  const int pd = tid >> 4, pt4 = tid & 15;      // prefetch mapping

  // issue prefetch for a slice into buffer `buf`
  auto prefetch = [&](int s, int buf) {
    if (tid < 224) {
      const int ga = pd * 128 + s * 16 + pt4;
      cpa16(qb0 + (uint32_t)(buf * 896 + (pd * 16 + pt4) * 4) * 4, gq + ga);
      cpa16(kb0 + (uint32_t)(buf * 896 + (pd * 16 + pt4) * 4) * 4, gk + ga);
      cpa16(vb0 + (uint32_t)(buf * 896 +
            (pd * 16 + (pt4 & 3) * 4 + (pt4 >> 2)) * 4) * 4, gv + ga);
    } else if (tid < 240) {
      const int t = tid - 224;
      cpa16(skb0 + (uint32_t)(buf * 64 + t * 4) * 4,
            (const float4*)(g_sk + sidx512 + s * 64) + t);
    } else {
      const int t = tid - 240;
      cpa16(sqb0 + (uint32_t)(buf * 64 + t * 4) * 4,
            (const float4*)(g_sq + sidx512 + s * 64) + t);
    }
  };

  prefetch(0, 0);
  cpa_commit();

  for (int Bs = 0; Bs < 8; Bs++) {
    const int buf = Bs & 1;
    __syncthreads();                 // prior FG done -> safe to refill buf
    if (Bs < 7) { prefetch(Bs + 1, buf ^ 1); cpa_commit(); }
    if (Bs < 7) cpa_wait<1>(); else cpa_wait<0>();
    __syncthreads();                 // slice Bs data visible block-wide

    const float4* q4 = (const float4*)q_s[buf];
    const float4* k4 = (const float4*)k_s[buf];
    const float4* v4 = (const float4*)v_s[buf];
    const float4* Sks4 = (const float4*)sks_s[buf];

    // ---- C: sim = q^T k (16i x 32j warp tile, 4x4 thread tile) ----
    {
      const int iq = wi * 4 + it2;
      const int cq = wj * 8 + jt2;
      float a00=0,a01=0,a02=0,a03=0, a10=0,a11=0,a12=0,a13=0;
      float a20=0,a21=0,a22=0,a23=0, a30=0,a31=0,a32=0,a33=0;
#pragma unroll
      for (int d = 0; d < 14; d++) {
        float4 qv = q4[d * 16 + iq];
        float4 kv = k4[d * 16 + cq];
        a00 += qv.x*kv.x; a01 += qv.x*kv.y; a02 += qv.x*kv.z; a03 += qv.x*kv.w;
        a10 += qv.y*kv.x; a11 += qv.y*kv.y; a12 += qv.y*kv.z; a13 += qv.y*kv.w;
        a20 += qv.z*kv.x; a21 += qv.z*kv.y; a22 += qv.z*kv.z; a23 += qv.z*kv.w;
        a30 += qv.w*kv.x; a31 += qv.w*kv.y; a32 += qv.w*kv.z; a33 += qv.w*kv.w;
      }
      const int rbase = iq * 4;
      sim4[(rbase+0) * 17 + cq] = make_float4(a00,a01,a02,a03);
      sim4[(rbase+1) * 17 + cq] = make_float4(a10,a11,a12,a13);
      sim4[(rbase+2) * 17 + cq] = make_float4(a20,a21,a22,a23);
      sim4[(rbase+3) * 17 + cq] = make_float4(a30,a31,a32,a33);
    }
    __syncthreads();

    // ---- FG: scale, softmax, mask, out-GEMM, store ----
    {
      const float sq = sq_s[buf][irow];
      const float th = theta_all[Bs];
      float a[16];
      float m = -1e30f;
#pragma unroll
      for (int c = 0; c < 4; c++) {
        float4 sv = sim4[irow * 17 + p4 * 4 + c];
        float4 kv = Sks4[c * 4 + p4];            // permuted Sk
        a[c*4+0] = sv.x * sq * kv.x; a[c*4+1] = sv.y * sq * kv.y;
        a[c*4+2] = sv.z * sq * kv.z; a[c*4+3] = sv.w * sq * kv.w;
        m = fmaxf(m, fmaxf(fmaxf(a[c*4+0], a[c*4+1]), fmaxf(a[c*4+2], a[c*4+3])));
      }
      m = fmaxf(m, __shfl_xor_sync(0xffffffffu, m, 1));
      m = fmaxf(m, __shfl_xor_sync(0xffffffffu, m, 2));
      float sum = 0.f;
#pragma unroll
      for (int e = 0; e < 16; e++) {
        float xv = a[e];
        float ev = __expf(xv - m);
        sum += ev;
        a[e] = (xv > th) ? ev : 0.f;
      }
      sum += __shfl_xor_sync(0xffffffffu, sum, 1);
      sum += __shfl_xor_sync(0xffffffffu, sum, 2);
      const float r = 1.f / sum;
#pragma unroll
      for (int e = 0; e < 16; e++) a[e] *= r;

      const size_t sp = (size_t)Bs * 16384 + hh * 128 + ww;
      const size_t cb = (size_t)(b * 112 + head * 28) * 131072 + sp;
#pragma unroll
      for (int half = 0; half < 2; half++) {
        float oacc[7] = {0.f,0.f,0.f,0.f,0.f,0.f,0.f};
#pragma unroll
        for (int dd = 0; dd < 7; dd++) {
          const int d = half * 7 + dd;
#pragma unroll
          for (int c = 0; c < 4; c++) {
            float4 vv = v4[d * 16 + c * 4 + p4];   // quarter-permuted v
            oacc[dd] += a[c*4+0]*vv.x + a[c*4+1]*vv.y
                      + a[c*4+2]*vv.z + a[c*4+3]*vv.w;
          }
        }
#pragma unroll
        for (int dd = 0; dd < 7; dd++) {
          float s = oacc[dd];
          s += __shfl_xor_sync(0xffffffffu, s, 1);
          s += __shfl_xor_sync(0xffffffffu, s, 2);
          oacc[dd] = s;
        }
#pragma unroll
        for (int k = 0; k < 2; k++) {
          const int dd = p4 + 4 * k;
          if (dd < 7) {
            const int d = half * 7 + dd;
            out[cb + (size_t)(2 * d)     * 131072] = oacc[dd] * woutc[d * 2 + 0];
            out[cb + (size_t)(2 * d + 1) * 131072] = oacc[dd] * woutc[d * 2 + 1];
          }
        }
      }
    }
  }
}

extern "C" void kernel_launch(void* const* d_in, const int* in_sizes, int n_in,
                              void* d_out, int out_size) {
  (void)in_sizes; (void)n_in; (void)out_size;
  const float* x      = (const float*)d_in[0];
  const float* last   = (const float*)d_in[1];
  const float* Wq     = (const float*)d_in[2];
  const float* Wk     = (const float*)d_in[3];
  const float* Wv     = (const float*)d_in[4];
  const float* Wout   = (const float*)d_in[5];
  const float* pcq_w  = (const float*)d_in[6];
  const float* pcq_b  = (const float*)d_in[7];
  const float* pck_w  = (const float*)d_in[8];
  const float* pck_b  = (const float*)d_in[9];
  const float* mlp1_w = (const float*)d_in[10];
  const float* mlp2w1 = (const float*)d_in[11];
  const float* mlp2w2 = (const float*)d_in[12];
  float* out = (float*)d_out;

  conv_all_kernel<<<dim3(1, 16, 336), dim3(32, 8)>>>(x, last, Wq, Wk, Wv);
  sigma_kernel<<<2048, 256>>>(pcq_w, pcq_b, pck_w, pck_b,
                              mlp1_w, mlp2w1, mlp2w2);
  attn_loop_kernel<<<2048, 256>>>(Wout, out);
}

// round 15
// speedup vs baseline: 1.0490x; 1.0490x over previous
#include <cuda_runtime.h>
#include <cstdint>

// qkv scratch in windowed layout: [b(2)][wy(16)][wx(16)][ch(56)][Bs(8)][tok(64)]
#define NELEM_QKV (2*16*16*56*8*64)
__device__ float g_q[NELEM_QKV];
__device__ float g_k[NELEM_QKV];
__device__ float g_v[NELEM_QKV];
// sigma scratch: [win*4+head][Bs][64] (Sk stored PERMUTED), theta: [sbid*8+Bs]
__device__ float g_sq[2048 * 512];
__device__ float g_sk[2048 * 512];
__device__ float g_theta[16384];

// ---------------------------------------------------------------------------
// Conv half-pass: computes output depths [HALF*4, HALF*4+4) for one (b,o,h).
// Input depths HALF*3 .. HALF*3+4. acc is 16 regs, scoped per call.
// ---------------------------------------------------------------------------
template <int HALF>
__device__ __forceinline__ void conv_half(
    const float* __restrict__ in, int b, int o, int h, int tx, int w0,
    const float* __restrict__ ws, float* __restrict__ op)
{
  float acc[4][4];
#pragma unroll
  for (int i = 0; i < 4; i++) {
    acc[i][0] = 0.f; acc[i][1] = 0.f; acc[i][2] = 0.f; acc[i][3] = 0.f;
  }

#pragma unroll
  for (int ci = 0; ci < 2; ci++) {
    const float* basec = in + (size_t)((b * 112 + o * 2 + ci) * 8) * 16384;
#pragma unroll
    for (int dh = 0; dh < 3; dh++) {
      const int hh = h + dh - 1;
      if (hh < 0 || hh > 127) continue;
      float w9[3][3];
#pragma unroll
      for (int kd = 0; kd < 3; kd++)
#pragma unroll
        for (int dw = 0; dw < 3; dw++)
          w9[kd][dw] = ws[ci * 27 + kd * 9 + dh * 3 + dw];
      const float* rowp = basec + hh * 128 + w0;
#pragma unroll
      for (int dd = 0; dd < 5; dd++) {
        const int d = HALF * 3 + dd;            // input depth
        const float* p = rowp + d * 16384;
        float4 m4 = *(const float4*)p;
        float vl = __shfl_up_sync(0xffffffffu, m4.w, 1);
        float vr = __shfl_down_sync(0xffffffffu, m4.x, 1);
        float v[6];
        v[0] = (tx == 0)  ? 0.f : vl;
        v[1] = m4.x; v[2] = m4.y; v[3] = m4.z; v[4] = m4.w;
        v[5] = (tx == 31) ? 0.f : vr;
#pragma unroll
        for (int kd = 0; kd < 3; kd++) {
          const int Bsl = dd + 1 - kd - HALF;   // local output depth
          if (Bsl < 0 || Bsl > 3) continue;     // compile-time DCE
#pragma unroll
          for (int dw = 0; dw < 3; dw++) {
            const float wv = w9[kd][dw];
            acc[Bsl][0] += wv * v[dw + 0];
            acc[Bsl][1] += wv * v[dw + 1];
            acc[Bsl][2] += wv * v[dw + 2];
            acc[Bsl][3] += wv * v[dw + 3];
          }
        }
      }
    }
  }

#pragma unroll
  for (int Bsl = 0; Bsl < 4; Bsl++) {
    *(float4*)(op + (HALF * 4 + Bsl) * 64) =
        make_float4(acc[Bsl][0], acc[Bsl][1], acc[Bsl][2], acc[Bsl][3]);
  }
}

// ---------------------------------------------------------------------------
// All three grouped 3x3x3 convs, one launch, two sequential Bs half-passes
// so the live accumulator set is 16 regs -> 4 blocks/SM.
// ---------------------------------------------------------------------------
__global__ __launch_bounds__(256, 4) void conv_all_kernel(
    const float* __restrict__ x, const float* __restrict__ last,
    const float* __restrict__ Wq, const float* __restrict__ Wk,
    const float* __restrict__ Wv)
{
  const int z = blockIdx.z;
  int idx, sel;
  if (z < 112) { idx = z; sel = 0; }
  else { int zz = z - 112; idx = zz >> 1; sel = 1 + (zz & 1); }
  const float* in = (sel == 0) ? x : last;
  const float* W3 = (sel == 0) ? Wq : (sel == 1) ? Wk : Wv;
  float* outw     = (sel == 0) ? g_q : (sel == 1) ? g_k : g_v;

  const int b = idx / 56, o = idx % 56;
  const int h = blockIdx.y * 8 + threadIdx.y;
  const int tx = threadIdx.x;
  const int w0 = tx * 4;

  __shared__ float ws[54];
  const int tid = threadIdx.y * 32 + tx;
  if (tid < 54) ws[tid] = W3[o * 54 + tid];
  __syncthreads();

  const int wy = h >> 3, ty = h & 7, wx = w0 >> 3, tx0 = w0 & 7;
  float* op = outw + (size_t)((((b * 16 + wy) * 16 + wx) * 56 + o) * 8) * 64
                   + ty * 8 + tx0;

  conv_half<0>(in, b, o, h, tx, w0, ws, op);
  conv_half<1>(in, b, o, h, tx, w0, ws, op);
}

// ---------------------------------------------------------------------------
// Sigma kernel: Sq, Sk (permuted), theta for all 8 slices.
// t1_i = q_i.Kbar - m1_i*(q_i.k_i).
// ---------------------------------------------------------------------------
__global__ __launch_bounds__(256) void sigma_kernel(
    const float* __restrict__ pcq_w, const float* __restrict__ pcq_b,
    const float* __restrict__ pck_w, const float* __restrict__ pck_b,
    const float* __restrict__ mlp1_w, const float* __restrict__ mlp2_w1,
    const float* __restrict__ mlp2_w2)
{
  __shared__ __align__(16) float m1[64], w2[64];
  __shared__ __align__(16) float kbar_s[128];    // [Bs][16]
  __shared__ __align__(16) float t1_all[512];    // [Bs][64]
  __shared__ __align__(16) float red2[512];
  __shared__ float pcqw[14], pckw[14];

  const int tid = threadIdx.x;
  const int bid = blockIdx.x;               // win*4 + head
  const int head = bid & 3, win = bid >> 2;
  const int b = win >> 8, wy = (win >> 4) & 15, wx = win & 15;

  if (tid < 64) { m1[tid] = mlp1_w[tid]; w2[tid] = mlp2_w2[tid]; }
  if (tid < 14) { pcqw[tid] = pcq_w[tid]; pckw[tid] = pck_w[tid]; }
  const float bq = pcq_b[0], bk = pck_b[0];

  const size_t wbase = (size_t)((b * 16 + wy) * 16 + wx) * (56 * 8 * 64);
  const float* gqf = g_q + wbase + head * 14 * 512;
  const float* gkf = g_k + wbase + head * 14 * 512;
  const float4* gk = (const float4*)gkf;
  const float4* m14 = (const float4*)m1;
  const float4* t14 = (const float4*)t1_all;
  const float4* w14 = (const float4*)mlp2_w1;
  __syncthreads();

  // P1: Kbar[Bs][d]
#pragma unroll
  for (int rep = 0; rep < 2; rep++) {
    const int item = rep * 64 + (tid >> 2);
    const int p4 = tid & 3;
    if (item < 112) {
      const int Bs = item / 14, d = item % 14;
      float pr = 0.f;
#pragma unroll
      for (int c = 0; c < 4; c++) {
        float4 kv = gk[d * 128 + Bs * 16 + p4 * 4 + c];
        float4 mm = m14[p4 * 4 + c];
        pr += kv.x*mm.x + kv.y*mm.y + kv.z*mm.z + kv.w*mm.w;
      }
      pr += __shfl_xor_sync(0xffffffffu, pr, 1);
      pr += __shfl_xor_sync(0xffffffffu, pr, 2);
      if (p4 == 0) kbar_s[Bs * 16 + d] = pr;
    }
  }
  __syncthreads();

  // P2: per (Bs,i): Sq, Sk (permuted), t1
#pragma unroll
  for (int rep = 0; rep < 2; rep++) {
    const int t = tid + rep * 256;
    const int Bs = t >> 6, i = t & 63;
    float sq = bq, sk = bk, qkb = 0.f, dg = 0.f;
#pragma unroll
    for (int d = 0; d < 14; d++) {
      float qv = gqf[d * 512 + Bs * 64 + i];
      float kv = gkf[d * 512 + Bs * 64 + i];
      sq  += qv * pcqw[d];
      sk  += kv * pckw[d];
      qkb += qv * kbar_s[Bs * 16 + d];
      dg  += qv * kv;
    }
    g_sq[(size_t)bid * 512 + Bs * 64 + i] = sq;
    g_sk[(size_t)bid * 512 + Bs * 64 +
         ((((i >> 2) & 3) * 4 + (i >> 4)) * 4 + (i & 3))] = sk;
    t1_all[Bs * 64 + i] = qkb - m1[i] * dg;
  }
  __syncthreads();

  // P3: t2 = leaky(t1 @ w1^T); red2 = t2 * w2
#pragma unroll
  for (int rep = 0; rep < 2; rep++) {
    const int t = tid + rep * 256;
    const int Bs = t >> 6, o = t & 63;
    float s = 0.f;
#pragma unroll
    for (int c = 0; c < 16; c++) {
      float4 wv = __ldg(&w14[o * 16 + c]);
      float4 tv = t14[Bs * 16 + c];
      s += wv.x*tv.x + wv.y*tv.y + wv.z*tv.z + wv.w*tv.w;
    }
    s = (s > 0.f) ? s : 0.1f * s;
    red2[Bs * 64 + o] = s * w2[o];
  }
  __syncthreads();

  // P4: theta[Bs]
  {
    const int w = tid >> 5, lane = tid & 31;
    float s = red2[w * 64 + lane] + red2[w * 64 + lane + 32];
#pragma unroll
    for (int off = 16; off > 0; off >>= 1)
      s += __shfl_xor_sync(0xffffffffu, s, off);
    if (lane == 0) g_theta[bid * 8 + w] = s;
  }
}

// ---------------------------------------------------------------------------
// Slice attention: one block per (win, head, Bs) = 16384 blocks (measured
// best form, R12). 16i x 32j C warp tile.
// ---------------------------------------------------------------------------
__global__ __launch_bounds__(256, 4) void attn_slice_kernel(
    const float* __restrict__ Wout, float* __restrict__ out)
{
  __shared__ __align__(16) float q_s[896], k_s[896], v_s[896];
  __shared__ __align__(16) float sim[64 * 68];
  __shared__ __align__(16) float sks[64];
  __shared__ float woutc[28];
  __shared__ float theta_sh;

  const int tid = threadIdx.x;
  const int bid = blockIdx.x;               // win*32 + head*8 + Bs
  const int Bs = bid & 7, head = (bid >> 3) & 3, win = bid >> 5;
  const int b = win >> 8, wy = (win >> 4) & 15, wx = win & 15;
  const int sidx = (bid >> 3) * 512 + Bs * 64;

  const size_t wbase = (size_t)((b * 16 + wy) * 16 + wx) * (56 * 8 * 64);
  const float4* gq = (const float4*)(g_q + wbase + head * 14 * 512);
  const float4* gk = (const float4*)(g_k + wbase + head * 14 * 512);
  const float4* gv = (const float4*)(g_v + wbase + head * 14 * 512);

  float4* q4 = (float4*)q_s; float4* k4 = (float4*)k_s; float4* v4 = (float4*)v_s;
  float4* sim4 = (float4*)sim;
  const float4* Sks4 = (const float4*)sks;

  const int irow = tid >> 2, p4 = tid & 3;      // FG quad ownership
  const int wi = (tid >> 5) & 3, wj = tid >> 7; // C warp tile
  const int lane = tid & 31;
  const int it2 = lane >> 3, jt2 = lane & 7;
  const int hh = wy * 8 + (irow >> 3), ww = wx * 8 + (irow & 7);

  if (tid < 224) {
    int d = tid >> 4, t4 = tid & 15;
    int ga = d * 128 + Bs * 16 + t4;
    q4[d * 16 + t4] = gq[ga];
    k4[d * 16 + t4] = gk[ga];
    v4[d * 16 + (t4 & 3) * 4 + (t4 >> 2)] = gv[ga];
  } else {
    int t = tid - 224;
    if (t < 16) ((float4*)sks)[t] = ((const float4*)(g_sk + sidx))[t];
    if (t < 28) woutc[t] = Wout[head * 28 + t];
    if (t == 28) theta_sh = g_theta[bid];
  }
  __syncthreads();

  // sim = q^T k: warp tile 16i x 32j, thread tile 4x4
  {
    const int iq = wi * 4 + it2;
    const int cq = wj * 8 + jt2;
    float a00=0,a01=0,a02=0,a03=0, a10=0,a11=0,a12=0,a13=0;
    float a20=0,a21=0,a22=0,a23=0, a30=0,a31=0,a32=0,a33=0;
#pragma unroll
    for (int d = 0; d < 14; d++) {
      float4 qv = q4[d * 16 + iq];
      float4 kv = k4[d * 16 + cq];
      a00 += qv.x*kv.x; a01 += qv.x*kv.y; a02 += qv.x*kv.z; a03 += qv.x*kv.w;
      a10 += qv.y*kv.x; a11 += qv.y*kv.y; a12 += qv.y*kv.z; a13 += qv.y*kv.w;
      a20 += qv.z*kv.x; a21 += qv.z*kv.y; a22 += qv.z*kv.z; a23 += qv.z*kv.w;
      a30 += qv.w*kv.x; a31 += qv.w*kv.y; a32 += qv.w*kv.z; a33 += qv.w*kv.w;
    }
    const int rbase = iq * 4;
    sim4[(rbase+0) * 17 + cq] = make_float4(a00,a01,a02,a03);
    sim4[(rbase+1) * 17 + cq] = make_float4(a10,a11,a12,a13);
    sim4[(rbase+2) * 17 + cq] = make_float4(a20,a21,a22,a23);
    sim4[(rbase+3) * 17 + cq] = make_float4(a30,a31,a32,a33);
  }
  __syncthreads();

  // scale, softmax, mask, out-GEMM, store
  {
    const float sq = g_sq[sidx + irow];
    const float th = theta_sh;
    float a[16];
    float m = -1e30f;
#pragma unroll
    for (int c = 0; c < 4; c++) {
      float4 sv = sim4[irow * 17 + p4 * 4 + c];
      float4 kv = Sks4[c * 4 + p4];
      a[c*4+0] = sv.x * sq * kv.x; a[c*4+1] = sv.y * sq * kv.y;
      a[c*4+2] = sv.z * sq * kv.z; a[c*4+3] = sv.w * sq * kv.w;
      m = fmaxf(m, fmaxf(fmaxf(a[c*4+0], a[c*4+1]), fmaxf(a[c*4+2], a[c*4+3])));
    }
    m = fmaxf(m, __shfl_xor_sync(0xffffffffu, m, 1));
    m = fmaxf(m, __shfl_xor_sync(0xffffffffu, m, 2));
    float sum = 0.f;
#pragma unroll
    for (int e = 0; e < 16; e++) {
      float xv = a[e];
      float ev = __expf(xv - m);
      sum += ev;
      a[e] = (xv > th) ? ev : 0.f;
    }
    sum += __shfl_xor_sync(0xffffffffu, sum, 1);
    sum += __shfl_xor_sync(0xffffffffu, sum, 2);
    const float r = 1.f / sum;
#pragma unroll
    for (int e = 0; e < 16; e++) a[e] *= r;

    const size_t sp = (size_t)Bs * 16384 + hh * 128 + ww;
    const size_t cb = (size_t)(b * 112 + head * 28) * 131072 + sp;
#pragma unroll
    for (int half = 0; half < 2; half++) {
      float oacc[7] = {0.f,0.f,0.f,0.f,0.f,0.f,0.f};
#pragma unroll
      for (int dd = 0; dd < 7; dd++) {
        const int d = half * 7 + dd;
#pragma unroll
        for (int c = 0; c < 4; c++) {
          float4 vv = v4[d * 16 + c * 4 + p4];
          oacc[dd] += a[c*4+0]*vv.x + a[c*4+1]*vv.y
                    + a[c*4+2]*vv.z + a[c*4+3]*vv.w;
        }
      }
#pragma unroll
      for (int dd = 0; dd < 7; dd++) {
        float s = oacc[dd];
        s += __shfl_xor_sync(0xffffffffu, s, 1);
        s += __shfl_xor_sync(0xffffffffu, s, 2);
        oacc[dd] = s;
      }
#pragma unroll
      for (int k = 0; k < 2; k++) {
        const int dd = p4 + 4 * k;
        if (dd < 7) {
          const int d = half * 7 + dd;
          out[cb + (size_t)(2 * d)     * 131072] = oacc[dd] * woutc[d * 2 + 0];
          out[cb + (size_t)(2 * d + 1) * 131072] = oacc[dd] * woutc[d * 2 + 1];
        }
      }
    }
  }
}

extern "C" void kernel_launch(void* const* d_in, const int* in_sizes, int n_in,
                              void* d_out, int out_size) {
  (void)in_sizes; (void)n_in; (void)out_size;
  const float* x      = (const float*)d_in[0];
  const float* last   = (const float*)d_in[1];
  const float* Wq     = (const float*)d_in[2];
  const float* Wk     = (const float*)d_in[3];
  const float* Wv     = (const float*)d_in[4];
  const float* Wout   = (const float*)d_in[5];
  const float* pcq_w  = (const float*)d_in[6];
  const float* pcq_b  = (const float*)d_in[7];
  const float* pck_w  = (const float*)d_in[8];
  const float* pck_b  = (const float*)d_in[9];
  const float* mlp1_w = (const float*)d_in[10];
  const float* mlp2w1 = (const float*)d_in[11];
  const float* mlp2w2 = (const float*)d_in[12];
  float* out = (float*)d_out;

  conv_all_kernel<<<dim3(1, 16, 336), dim3(32, 8)>>>(x, last, Wq, Wk, Wv);
  sigma_kernel<<<2048, 256>>>(pcq_w, pcq_b, pck_w, pck_b,
                              mlp1_w, mlp2w1, mlp2w2);
  attn_slice_kernel<<<16384, 256>>>(Wout, out);
}